// round 2
// baseline (speedup 1.0000x reference)
#include <cuda_runtime.h>

// Problem constants (fixed by the reference setup_inputs)
#define B_   16384
#define DIN  1024
#define D_   512
#define K_   8192

// Tiling
#define TM   128
#define TN   128
#define KC   16
#define SSTR 132   // padded shared stride

// Scratch (allocations are forbidden; device globals are the sanctioned path)
__device__ float g_ze[(size_t)B_ * D_];   // z_e  [B, D]
__device__ float g_c2[K_];                // |c_k|^2
__device__ float g_zz[B_];                // |z_e_b|^2
__device__ int   g_idx[B_];               // argmin indices

// ---------------------------------------------------------------------------
// Kernel: codebook squared norms. One warp per codebook row.
// ---------------------------------------------------------------------------
__global__ void c2_kernel(const float* __restrict__ cb) {
    int row  = blockIdx.x * 8 + (threadIdx.x >> 5);
    int lane = threadIdx.x & 31;
    const float* p = cb + (size_t)row * D_;
    float s = 0.f;
    #pragma unroll 4
    for (int i = lane; i < D_; i += 32) { float v = p[i]; s += v * v; }
    #pragma unroll
    for (int o = 16; o; o >>= 1) s += __shfl_xor_sync(0xffffffffu, s, o);
    if (lane == 0) g_c2[row] = s;
}

// ---------------------------------------------------------------------------
// Kernel: per-row |z_e|^2. fp64 accumulation, rounded once to fp32 (stable
// high-accuracy stand-in for the reference's fp32 row sum).
// One warp per B-row.
// ---------------------------------------------------------------------------
__global__ void zz_kernel() {
    int row  = blockIdx.x * 8 + (threadIdx.x >> 5);
    int lane = threadIdx.x & 31;
    const float* p = g_ze + (size_t)row * D_;
    double s = 0.0;
    #pragma unroll 4
    for (int i = lane; i < D_; i += 32) { double v = (double)p[i]; s += v * v; }
    #pragma unroll
    for (int o = 16; o; o >>= 1) s += __shfl_xor_sync(0xffffffffu, s, o);
    if (lane == 0) g_zz[row] = (float)s;
}

// ---------------------------------------------------------------------------
// Tile load/store helpers: 128 rows x 16 cols fp32 tile via float4.
// Tile stored transposed into smem as [KC][SSTR].
// ---------------------------------------------------------------------------
__device__ __forceinline__ void load_tile(float4 v[2], const float* __restrict__ base,
                                          int row0, int ld, int d0, int tid) {
    #pragma unroll
    for (int i = 0; i < 2; i++) {
        int idx = tid + i * 256;
        int r   = idx >> 2;
        int c4  = idx & 3;
        v[i] = *reinterpret_cast<const float4*>(base + (size_t)(row0 + r) * ld + d0 + c4 * 4);
    }
}

__device__ __forceinline__ void store_tile(const float4 v[2], float* s, int tid) {
    #pragma unroll
    for (int i = 0; i < 2; i++) {
        int idx = tid + i * 256;
        int r   = idx >> 2;
        int c4  = idx & 3;
        s[(c4 * 4 + 0) * SSTR + r] = v[i].x;
        s[(c4 * 4 + 1) * SSTR + r] = v[i].y;
        s[(c4 * 4 + 2) * SSTR + r] = v[i].z;
        s[(c4 * 4 + 3) * SSTR + r] = v[i].w;
    }
}

// ---------------------------------------------------------------------------
// Kernel: GEMM1  z_e = x @ W^T
// ---------------------------------------------------------------------------
__global__ __launch_bounds__(256) void gemm1_kernel(const float* __restrict__ A,
                                                    const float* __restrict__ Wm) {
    __shared__ float As[KC * SSTR];
    __shared__ float Bs[KC * SSTR];

    const int tid = threadIdx.x;
    const int tx  = tid & 15;
    const int ty  = tid >> 4;
    const int row0 = blockIdx.y * TM;
    const int col0 = blockIdx.x * TN;

    float acc[8][8];
    #pragma unroll
    for (int i = 0; i < 8; i++)
        #pragma unroll
        for (int j = 0; j < 8; j++) acc[i][j] = 0.f;

    const int NCH = DIN / KC;  // 64
    float4 pa[2], pb[2];
    load_tile(pa, A,  row0, DIN, 0, tid);
    load_tile(pb, Wm, col0, DIN, 0, tid);

    for (int ch = 0; ch < NCH; ch++) {
        store_tile(pa, As, tid);
        store_tile(pb, Bs, tid);
        __syncthreads();
        if (ch + 1 < NCH) {
            int d0 = (ch + 1) * KC;
            load_tile(pa, A,  row0, DIN, d0, tid);
            load_tile(pb, Wm, col0, DIN, d0, tid);
        }
        #pragma unroll
        for (int kk = 0; kk < KC; kk++) {
            float a[8], b[8];
            #pragma unroll
            for (int i = 0; i < 8; i++) a[i] = As[kk * SSTR + ty * 8 + i];
            #pragma unroll
            for (int j = 0; j < 8; j++) b[j] = Bs[kk * SSTR + tx * 8 + j];
            #pragma unroll
            for (int i = 0; i < 8; i++)
                #pragma unroll
                for (int j = 0; j < 8; j++) acc[i][j] += a[i] * b[j];
        }
        __syncthreads();
    }

    #pragma unroll
    for (int i = 0; i < 8; i++) {
        float* o = g_ze + (size_t)(row0 + ty * 8 + i) * D_ + col0 + tx * 8;
        #pragma unroll
        for (int j = 0; j < 8; j++) o[j] = acc[i][j];
    }
}

// ---------------------------------------------------------------------------
// Kernel: GEMM2 + fused argmin.
// Comparison value REPLICATES the reference's fp32 numerics:
//   v = fl32( fl32(|z|^2 - 2*dot) + |c|^2 )
// The row-constant |z|^2 (~645) sets the same ~6e-5 fp32 quantization grid
// the reference has, so near-tie codes collapse to EQUAL fp32 values and the
// first-index (lowest k) tie-break below matches jnp.argmin.
// ---------------------------------------------------------------------------
__global__ __launch_bounds__(256) void vq_argmin_kernel(const float* __restrict__ cb) {
    __shared__ float As[KC * SSTR];
    __shared__ float Bs[KC * SSTR];
    __shared__ float s_rv[TM * 16];
    __shared__ int   s_ri[TM * 16];

    const int tid = threadIdx.x;
    const int tx  = tid & 15;
    const int ty  = tid >> 4;
    const int row0 = blockIdx.x * TM;

    float bval[8];
    int   bidx[8];
    #pragma unroll
    for (int i = 0; i < 8; i++) { bval[i] = 3.4e38f; bidx[i] = 0x7fffffff; }

    float zzi[8];
    #pragma unroll
    for (int i = 0; i < 8; i++) zzi[i] = g_zz[row0 + ty * 8 + i];

    const int NKT  = K_ / TN;  // 64
    const int NCH2 = D_ / KC;  // 32
    const float* zbase = g_ze;

    for (int kt = 0; kt < NKT; kt++) {
        const int k0 = kt * TN;

        float acc[8][8];
        #pragma unroll
        for (int i = 0; i < 8; i++)
            #pragma unroll
            for (int j = 0; j < 8; j++) acc[i][j] = 0.f;

        float4 pa[2], pb[2];
        load_tile(pa, zbase, row0, D_, 0, tid);
        load_tile(pb, cb,    k0,   D_, 0, tid);

        for (int ch = 0; ch < NCH2; ch++) {
            __syncthreads();   // previous compute done before smem overwrite
            store_tile(pa, As, tid);
            store_tile(pb, Bs, tid);
            __syncthreads();
            if (ch + 1 < NCH2) {
                int d0 = (ch + 1) * KC;
                load_tile(pa, zbase, row0, D_, d0, tid);
                load_tile(pb, cb,    k0,   D_, d0, tid);
            }
            #pragma unroll
            for (int kk = 0; kk < KC; kk++) {
                float a[8], b[8];
                #pragma unroll
                for (int i = 0; i < 8; i++) a[i] = As[kk * SSTR + ty * 8 + i];
                #pragma unroll
                for (int j = 0; j < 8; j++) b[j] = Bs[kk * SSTR + tx * 8 + j];
                #pragma unroll
                for (int i = 0; i < 8; i++)
                    #pragma unroll
                    for (int j = 0; j < 8; j++) acc[i][j] += a[i] * b[j];
            }
        }

        // Epilogue: fold this code tile into the running min using the
        // reference's fp32 rounding structure.
        float c2v[8];
        #pragma unroll
        for (int j = 0; j < 8; j++) c2v[j] = g_c2[k0 + tx * 8 + j];
        #pragma unroll
        for (int i = 0; i < 8; i++) {
            #pragma unroll
            for (int j = 0; j < 8; j++) {
                float t = __fadd_rn(zzi[i], -2.f * acc[i][j]);  // fl32(zz - 2*dot)
                float v = __fadd_rn(t, c2v[j]);                 // fl32(... + |c|^2)
                int   ki = k0 + tx * 8 + j;
                if (v < bval[i] || (v == bval[i] && ki < bidx[i])) {
                    bval[i] = v; bidx[i] = ki;
                }
            }
        }
    }

    __syncthreads();
    #pragma unroll
    for (int i = 0; i < 8; i++) {
        s_rv[(ty * 8 + i) * 16 + tx] = bval[i];
        s_ri[(ty * 8 + i) * 16 + tx] = bidx[i];
    }
    __syncthreads();

    if (tid < TM) {
        float bv = s_rv[tid * 16];
        int   bi = s_ri[tid * 16];
        #pragma unroll
        for (int t = 1; t < 16; t++) {
            float v  = s_rv[tid * 16 + t];
            int   ii = s_ri[tid * 16 + t];
            if (v < bv || (v == bv && ii < bi)) { bv = v; bi = ii; }
        }
        g_idx[row0 + tid] = bi;
    }
}

// ---------------------------------------------------------------------------
// Kernel: output assembly. One block (128 threads) per B-row.
// out layout (f32): [ z_q_st : B*D ][ indices : B ][ vq_loss : B ]
// ---------------------------------------------------------------------------
__global__ void output_kernel(const float* __restrict__ cb, float* __restrict__ out) {
    const int b   = blockIdx.x;
    const int tid = threadIdx.x;
    const int idx = g_idx[b];

    const float* ze = g_ze + (size_t)b * D_;
    const float* zq = cb   + (size_t)idx * D_;
    float*       o  = out  + (size_t)b * D_;

    float s = 0.f;
    #pragma unroll
    for (int d = tid; d < D_; d += 128) {
        float e    = ze[d];
        float q    = zq[d];
        float diff = q - e;            // stop_grad(z_q - z_e)
        o[d] = e + diff;               // straight-through forward
        s += diff * diff;
    }

    __shared__ float red[128];
    red[tid] = s;
    __syncthreads();
    #pragma unroll
    for (int o2 = 64; o2; o2 >>= 1) {
        if (tid < o2) red[tid] += red[tid + o2];
        __syncthreads();
    }
    if (tid == 0) {
        out[(size_t)B_ * D_ + b]      = (float)idx;          // indices
        out[(size_t)B_ * D_ + B_ + b] = red[0] / (float)D_;  // vq_loss
    }
}

// ---------------------------------------------------------------------------
extern "C" void kernel_launch(void* const* d_in, const int* in_sizes, int n_in,
                              void* d_out, int out_size) {
    const float* x  = (const float*)d_in[0];   // [B, DIN]
    const float* W  = (const float*)d_in[1];   // [D, DIN]
    const float* cb = (const float*)d_in[2];   // [K, D]
    float* out = (float*)d_out;

    (void)in_sizes; (void)n_in; (void)out_size;

    c2_kernel<<<K_ / 8, 256>>>(cb);
    gemm1_kernel<<<dim3(D_ / TN, B_ / TM), 256>>>(x, W);
    zz_kernel<<<B_ / 8, 256>>>();
    vq_argmin_kernel<<<B_ / TM, 256>>>(cb);
    output_kernel<<<B_, 128>>>(cb, out);
}

// round 4
// speedup vs baseline: 2.1477x; 2.1477x over previous
#include <cuda_runtime.h>
#include <cuda_bf16.h>
#include <cstdint>

// Problem constants
#define B_   16384
#define DIN  1024
#define D_   512
#define K_   8192
#define KP   1536          // extended split-K: [a0|a0|a1] . [b0|b1|b0]

// SIMT GEMM1 tiling
#define TM   128
#define TN   128
#define KC   16
#define SSTR 132

// ---------------------------------------------------------------------------
// Scratch (device globals; allocations forbidden)
// ---------------------------------------------------------------------------
__device__ float g_ze[(size_t)B_ * D_];   // z_e fp32
__device__ float g_c2[K_];
__device__ float g_zz[B_];
__device__ int   g_idx[B_];
__device__ __nv_bfloat16 g_zs[(size_t)B_ * KP];   // packed z_e splits
__device__ __nv_bfloat16 g_cs[(size_t)K_ * KP];   // packed codebook splits

// ---------------------------------------------------------------------------
// PTX helpers (baseline PTX only: works at .target sm_100)
// ---------------------------------------------------------------------------
__device__ __forceinline__ uint32_t smem_u32(const void* p) {
    uint32_t a;
    asm("{ .reg .u64 t; cvta.to.shared.u64 t, %1; cvt.u32.u64 %0, t; }" : "=r"(a) : "l"(p));
    return a;
}
__device__ __forceinline__ void cp_async16(uint32_t saddr, const void* gaddr) {
    asm volatile("cp.async.cg.shared.global [%0], [%1], 16;" :: "r"(saddr), "l"(gaddr));
}
__device__ __forceinline__ void cp_commit() { asm volatile("cp.async.commit_group;"); }
__device__ __forceinline__ void cp_wait1()  { asm volatile("cp.async.wait_group 1;" ::: "memory"); }

__device__ __forceinline__ void ldsm_x4(uint32_t& r0, uint32_t& r1, uint32_t& r2, uint32_t& r3,
                                        uint32_t addr) {
    asm volatile("ldmatrix.sync.aligned.m8n8.x4.shared.b16 {%0,%1,%2,%3}, [%4];"
                 : "=r"(r0), "=r"(r1), "=r"(r2), "=r"(r3) : "r"(addr));
}
__device__ __forceinline__ void mma_bf16(float* c, const uint32_t* a, uint32_t b0, uint32_t b1) {
    asm volatile("mma.sync.aligned.m16n8k16.row.col.f32.bf16.bf16.f32 "
                 "{%0,%1,%2,%3}, {%4,%5,%6,%7}, {%8,%9}, {%0,%1,%2,%3};"
                 : "+f"(c[0]), "+f"(c[1]), "+f"(c[2]), "+f"(c[3])
                 : "r"(a[0]), "r"(a[1]), "r"(a[2]), "r"(a[3]), "r"(b0), "r"(b1));
}

// ---------------------------------------------------------------------------
// c2 / zz
// ---------------------------------------------------------------------------
__global__ void c2_kernel(const float* __restrict__ cb) {
    int row  = blockIdx.x * 8 + (threadIdx.x >> 5);
    int lane = threadIdx.x & 31;
    const float* p = cb + (size_t)row * D_;
    float s = 0.f;
    #pragma unroll 4
    for (int i = lane; i < D_; i += 32) { float v = p[i]; s += v * v; }
    #pragma unroll
    for (int o = 16; o; o >>= 1) s += __shfl_xor_sync(0xffffffffu, s, o);
    if (lane == 0) g_c2[row] = s;
}

__global__ void zz_kernel() {
    int row  = blockIdx.x * 8 + (threadIdx.x >> 5);
    int lane = threadIdx.x & 31;
    const float* p = g_ze + (size_t)row * D_;
    double s = 0.0;
    #pragma unroll 4
    for (int i = lane; i < D_; i += 32) { double v = (double)p[i]; s += v * v; }
    #pragma unroll
    for (int o = 16; o; o >>= 1) s += __shfl_xor_sync(0xffffffffu, s, o);
    if (lane == 0) g_zz[row] = (float)s;
}

// ---------------------------------------------------------------------------
// Split-pack kernels. One block of 128 threads per source row (4 elems each).
//   z row: [0,512)=a0  [512,1024)=a0  [1024,1536)=a1
//   c row: [0,512)=b0  [512,1024)=b1  [1024,1536)=b0
// ---------------------------------------------------------------------------
__global__ void pack_z_kernel() {
    const int row = blockIdx.x, t = threadIdx.x;
    float4 x = *reinterpret_cast<const float4*>(g_ze + (size_t)row * D_ + t * 4);
    __nv_bfloat162 h01, h23, l01, l23;
    h01.x = __float2bfloat16_rn(x.x); h01.y = __float2bfloat16_rn(x.y);
    h23.x = __float2bfloat16_rn(x.z); h23.y = __float2bfloat16_rn(x.w);
    l01.x = __float2bfloat16_rn(x.x - __bfloat162float(h01.x));
    l01.y = __float2bfloat16_rn(x.y - __bfloat162float(h01.y));
    l23.x = __float2bfloat16_rn(x.z - __bfloat162float(h23.x));
    l23.y = __float2bfloat16_rn(x.w - __bfloat162float(h23.y));
    __nv_bfloat162* d = reinterpret_cast<__nv_bfloat162*>(g_zs + (size_t)row * KP + t * 4);
    d[0] = h01; d[1] = h23;
    d += 256;  d[0] = h01; d[1] = h23;      // +512 elems: a0 again
    d += 256;  d[0] = l01; d[1] = l23;      // +1024: a1
}

__global__ void pack_c_kernel(const float* __restrict__ cb) {
    const int row = blockIdx.x, t = threadIdx.x;
    float4 x = *reinterpret_cast<const float4*>(cb + (size_t)row * D_ + t * 4);
    __nv_bfloat162 h01, h23, l01, l23;
    h01.x = __float2bfloat16_rn(x.x); h01.y = __float2bfloat16_rn(x.y);
    h23.x = __float2bfloat16_rn(x.z); h23.y = __float2bfloat16_rn(x.w);
    l01.x = __float2bfloat16_rn(x.x - __bfloat162float(h01.x));
    l01.y = __float2bfloat16_rn(x.y - __bfloat162float(h01.y));
    l23.x = __float2bfloat16_rn(x.z - __bfloat162float(h23.x));
    l23.y = __float2bfloat16_rn(x.w - __bfloat162float(h23.y));
    __nv_bfloat162* d = reinterpret_cast<__nv_bfloat162*>(g_cs + (size_t)row * KP + t * 4);
    d[0] = h01; d[1] = h23;
    d += 256;  d[0] = l01; d[1] = l23;      // +512: b1
    d += 256;  d[0] = h01; d[1] = h23;      // +1024: b0 again
}

// ---------------------------------------------------------------------------
// SIMT GEMM1 (fp32, at FFMA roofline for its size)
// ---------------------------------------------------------------------------
__device__ __forceinline__ void load_tile(float4 v[2], const float* __restrict__ base,
                                          int row0, int ld, int d0, int tid) {
    #pragma unroll
    for (int i = 0; i < 2; i++) {
        int idx = tid + i * 256;
        int r   = idx >> 2;
        int c4  = idx & 3;
        v[i] = *reinterpret_cast<const float4*>(base + (size_t)(row0 + r) * ld + d0 + c4 * 4);
    }
}
__device__ __forceinline__ void store_tile(const float4 v[2], float* s, int tid) {
    #pragma unroll
    for (int i = 0; i < 2; i++) {
        int idx = tid + i * 256;
        int r   = idx >> 2;
        int c4  = idx & 3;
        s[(c4 * 4 + 0) * SSTR + r] = v[i].x;
        s[(c4 * 4 + 1) * SSTR + r] = v[i].y;
        s[(c4 * 4 + 2) * SSTR + r] = v[i].z;
        s[(c4 * 4 + 3) * SSTR + r] = v[i].w;
    }
}

__global__ __launch_bounds__(256) void gemm1_kernel(const float* __restrict__ A,
                                                    const float* __restrict__ Wm) {
    __shared__ float As[KC * SSTR];
    __shared__ float Bs[KC * SSTR];
    const int tid = threadIdx.x;
    const int tx  = tid & 15;
    const int ty  = tid >> 4;
    const int row0 = blockIdx.y * TM;
    const int col0 = blockIdx.x * TN;

    float acc[8][8];
    #pragma unroll
    for (int i = 0; i < 8; i++)
        #pragma unroll
        for (int j = 0; j < 8; j++) acc[i][j] = 0.f;

    const int NCH = DIN / KC;
    float4 pa[2], pb[2];
    load_tile(pa, A,  row0, DIN, 0, tid);
    load_tile(pb, Wm, col0, DIN, 0, tid);

    for (int ch = 0; ch < NCH; ch++) {
        store_tile(pa, As, tid);
        store_tile(pb, Bs, tid);
        __syncthreads();
        if (ch + 1 < NCH) {
            int d0 = (ch + 1) * KC;
            load_tile(pa, A,  row0, DIN, d0, tid);
            load_tile(pb, Wm, col0, DIN, d0, tid);
        }
        #pragma unroll
        for (int kk = 0; kk < KC; kk++) {
            float a[8], b[8];
            #pragma unroll
            for (int i = 0; i < 8; i++) a[i] = As[kk * SSTR + ty * 8 + i];
            #pragma unroll
            for (int j = 0; j < 8; j++) b[j] = Bs[kk * SSTR + tx * 8 + j];
            #pragma unroll
            for (int i = 0; i < 8; i++)
                #pragma unroll
                for (int j = 0; j < 8; j++) acc[i][j] += a[i] * b[j];
        }
        __syncthreads();
    }
    #pragma unroll
    for (int i = 0; i < 8; i++) {
        float* o = g_ze + (size_t)(row0 + ty * 8 + i) * D_ + col0 + tx * 8;
        #pragma unroll
        for (int j = 0; j < 8; j++) o[j] = acc[i][j];
    }
}

// ---------------------------------------------------------------------------
// mma.sync GEMM2 + fused argmin.
// Block = 128 z-rows. Loop 64 code tiles of 128. K'=1536, BLK_K=64, 3-stage
// cp.async pipeline. 8 warps, warp tile 64x32 (warp_m=wid&1, warp_n=wid>>1).
// Epilogue folds the quantization-replicated distance into a per-thread
// running (val,idx) min; final 16-way smem reduction per row.
// ---------------------------------------------------------------------------
#define NS     3
#define BLKK   64
#define NKIT   (KP / BLKK)            // 24
#define STAGEB 16384                  // 128 rows x 128B per stage
#define SMB_B  (NS * STAGEB)          // B region offset = 49152
#define SMTOT  (2 * NS * STAGEB)      // 98304

__global__ __launch_bounds__(256, 1) void vq_mma_kernel() {
    extern __shared__ char sm[];
    const uint32_t sbase = smem_u32(sm);
    const int tid  = threadIdx.x;
    const int lane = tid & 31;
    const int wid  = tid >> 5;
    const int warp_m = wid & 1;        // 0..1 -> 64-row halves
    const int warp_n = wid >> 1;       // 0..3 -> 32-col quarters
    const int row0 = blockIdx.x * 128;

    // this thread's 8 accumulator rows: warp_m*64 + mf*16 + h*8 + lane/4
    float zz[8];
    #pragma unroll
    for (int mf = 0; mf < 4; mf++)
        #pragma unroll
        for (int h = 0; h < 2; h++)
            zz[mf * 2 + h] = g_zz[row0 + warp_m * 64 + mf * 16 + h * 8 + (lane >> 2)];

    float bv[8];
    int   bi[8];
    #pragma unroll
    for (int i = 0; i < 8; i++) { bv[i] = 3.4e38f; bi[i] = 0x7fffffff; }

    const __nv_bfloat16* gA = g_zs + (size_t)row0 * KP;

    for (int nt = 0; nt < 64; nt++) {
        const __nv_bfloat16* gB = g_cs + (size_t)(nt * 128) * KP;

        float acc[4][4][4];
        #pragma unroll
        for (int mf = 0; mf < 4; mf++)
            #pragma unroll
            for (int nf = 0; nf < 4; nf++)
                #pragma unroll
                for (int q = 0; q < 4; q++) acc[mf][nf][q] = 0.f;

        // --- async stage loader: A and B tiles, 128 rows x 64 bf16, swizzled ---
        #define ISSUE_STAGE(stg, kit) do {                                         \
            const uint32_t As_ = sbase + (stg) * STAGEB;                           \
            const uint32_t Bs_ = sbase + SMB_B + (stg) * STAGEB;                   \
            const int koff_ = (kit) * BLKK;                                       \
            _Pragma("unroll")                                                      \
            for (int i_ = 0; i_ < 4; i_++) {                                       \
                int id_ = tid + i_ * 256;                                          \
                int r_  = id_ >> 3;                                                \
                int c_  = id_ & 7;                                                 \
                int cp_ = c_ ^ (r_ & 7);                                           \
                cp_async16(As_ + r_ * 128 + cp_ * 16, gA + (size_t)r_ * KP + koff_ + c_ * 8); \
                cp_async16(Bs_ + r_ * 128 + cp_ * 16, gB + (size_t)r_ * KP + koff_ + c_ * 8); \
            }                                                                      \
        } while (0)

        ISSUE_STAGE(0, 0); cp_commit();
        ISSUE_STAGE(1, 1); cp_commit();

        for (int kit = 0; kit < NKIT; kit++) {
            cp_wait1();
            __syncthreads();
            if (kit + 2 < NKIT) ISSUE_STAGE((kit + 2) % NS, kit + 2);
            cp_commit();

            const int stg = kit % NS;
            const uint32_t Abase = sbase + stg * STAGEB;
            const uint32_t Bbase = sbase + SMB_B + stg * STAGEB;
            const int g = lane >> 3;
            const int r8 = lane & 7;

            #pragma unroll
            for (int ks = 0; ks < 4; ks++) {
                uint32_t afr[4][4];
                #pragma unroll
                for (int mf = 0; mf < 4; mf++) {
                    int rr = warp_m * 64 + mf * 16 + ((g & 1) << 3) + r8;
                    int ch = 2 * ks + (g >> 1);
                    ldsm_x4(afr[mf][0], afr[mf][1], afr[mf][2], afr[mf][3],
                            Abase + rr * 128 + ((ch ^ (rr & 7)) << 4));
                }
                uint32_t bfr[2][4];
                #pragma unroll
                for (int nf2 = 0; nf2 < 2; nf2++) {
                    int rr = warp_n * 32 + nf2 * 16 + ((g >> 1) << 3) + r8;
                    int ch = 2 * ks + (g & 1);
                    ldsm_x4(bfr[nf2][0], bfr[nf2][1], bfr[nf2][2], bfr[nf2][3],
                            Bbase + rr * 128 + ((ch ^ (rr & 7)) << 4));
                }
                #pragma unroll
                for (int mf = 0; mf < 4; mf++)
                    #pragma unroll
                    for (int nf = 0; nf < 4; nf++)
                        mma_bf16(acc[mf][nf], afr[mf],
                                 bfr[nf >> 1][(nf & 1) * 2], bfr[nf >> 1][(nf & 1) * 2 + 1]);
            }
        }
        #undef ISSUE_STAGE

        // --- epilogue: fold tile into running min (reference fp32 rounding) ---
        #pragma unroll
        for (int nf = 0; nf < 4; nf++) {
            const int code0 = nt * 128 + warp_n * 32 + nf * 8 + (lane & 3) * 2;
            const float c2a = __ldg(&g_c2[code0]);
            const float c2b = __ldg(&g_c2[code0 + 1]);
            #pragma unroll
            for (int mf = 0; mf < 4; mf++) {
                #pragma unroll
                for (int h = 0; h < 2; h++) {
                    const int ridx = mf * 2 + h;
                    float t0 = __fadd_rn(zz[ridx], -2.0f * acc[mf][nf][h * 2 + 0]);
                    float v0 = __fadd_rn(t0, c2a);
                    float t1 = __fadd_rn(zz[ridx], -2.0f * acc[mf][nf][h * 2 + 1]);
                    float v1 = __fadd_rn(t1, c2b);
                    if (v0 < bv[ridx] || (v0 == bv[ridx] && code0 < bi[ridx])) {
                        bv[ridx] = v0; bi[ridx] = code0;
                    }
                    if (v1 < bv[ridx] || (v1 == bv[ridx] && code0 + 1 < bi[ridx])) {
                        bv[ridx] = v1; bi[ridx] = code0 + 1;
                    }
                }
            }
        }
    }

    // --- final reduction: 16 owners per row (4 warp_n x 4 lane%4) ---
    __syncthreads();
    float* mv = reinterpret_cast<float*>(sm);              // [128][16]
    int*   mi = reinterpret_cast<int*>(sm + 128 * 16 * 4); // [128][16]
    const int slot = warp_n * 4 + (lane & 3);
    #pragma unroll
    for (int ridx = 0; ridx < 8; ridx++) {
        int row = warp_m * 64 + (ridx >> 1) * 16 + (ridx & 1) * 8 + (lane >> 2);
        mv[row * 16 + slot] = bv[ridx];
        mi[row * 16 + slot] = bi[ridx];
    }
    __syncthreads();
    if (tid < 128) {
        float v = mv[tid * 16];
        int   b = mi[tid * 16];
        #pragma unroll
        for (int t = 1; t < 16; t++) {
            float v2 = mv[tid * 16 + t];
            int   b2 = mi[tid * 16 + t];
            if (v2 < v || (v2 == v && b2 < b)) { v = v2; b = b2; }
        }
        g_idx[row0 + tid] = b;
    }
}

// ---------------------------------------------------------------------------
// Output assembly
// ---------------------------------------------------------------------------
__global__ void output_kernel(const float* __restrict__ cb, float* __restrict__ out) {
    const int b   = blockIdx.x;
    const int tid = threadIdx.x;
    const int idx = g_idx[b];

    const float* ze = g_ze + (size_t)b * D_;
    const float* zq = cb   + (size_t)idx * D_;
    float*       o  = out  + (size_t)b * D_;

    float s = 0.f;
    #pragma unroll
    for (int d = tid; d < D_; d += 128) {
        float e    = ze[d];
        float q    = zq[d];
        float diff = q - e;
        o[d] = e + diff;
        s += diff * diff;
    }
    __shared__ float red[128];
    red[tid] = s;
    __syncthreads();
    #pragma unroll
    for (int o2 = 64; o2; o2 >>= 1) {
        if (tid < o2) red[tid] += red[tid + o2];
        __syncthreads();
    }
    if (tid == 0) {
        out[(size_t)B_ * D_ + b]      = (float)idx;
        out[(size_t)B_ * D_ + B_ + b] = red[0] / (float)D_;
    }
}

// ---------------------------------------------------------------------------
extern "C" void kernel_launch(void* const* d_in, const int* in_sizes, int n_in,
                              void* d_out, int out_size) {
    const float* x  = (const float*)d_in[0];
    const float* W  = (const float*)d_in[1];
    const float* cb = (const float*)d_in[2];
    float* out = (float*)d_out;
    (void)in_sizes; (void)n_in; (void)out_size;

    cudaFuncSetAttribute(vq_mma_kernel, cudaFuncAttributeMaxDynamicSharedMemorySize, SMTOT);

    c2_kernel<<<K_ / 8, 256>>>(cb);
    pack_c_kernel<<<K_, 128>>>(cb);
    gemm1_kernel<<<dim3(D_ / TN, B_ / TM), 256>>>(x, W);
    zz_kernel<<<B_ / 8, 256>>>();
    pack_z_kernel<<<B_, 128>>>();
    vq_mma_kernel<<<B_ / 128, 256, SMTOT>>>();
    output_kernel<<<B_, 128>>>(cb, out);
}

// round 5
// speedup vs baseline: 4.7141x; 2.1949x over previous
#include <cuda_runtime.h>
#include <cuda_bf16.h>
#include <cstdint>

// Problem constants
#define B_   16384
#define DIN  1024
#define D_   512
#define K_   8192
#define KP2  3072          // gemm1 packed K: [a0|a0|a1] . [b0|b1|b0]

// ---------------------------------------------------------------------------
// Scratch (device globals; allocations forbidden)
// ---------------------------------------------------------------------------
__device__ float g_ze[(size_t)B_ * D_];     // z_e fp32
__device__ float g_c2[K_];
__device__ float g_zz[B_];
__device__ int   g_idx[B_];
__device__ float g_dist[(size_t)B_ * K_];   // approx scores, 512MB
__device__ __nv_bfloat16 g_xs[(size_t)B_ * KP2];   // packed x splits
__device__ __nv_bfloat16 g_ws[(size_t)D_ * KP2];   // packed W splits
__device__ __nv_bfloat16 g_zb[(size_t)B_ * D_];    // bf16(z_e), single split
__device__ __nv_bfloat16 g_cbb[(size_t)K_ * D_];   // bf16(cb),  single split

// ---------------------------------------------------------------------------
// PTX helpers (baseline PTX only: works at .target sm_100)
// ---------------------------------------------------------------------------
__device__ __forceinline__ uint32_t smem_u32(const void* p) {
    uint32_t a;
    asm("{ .reg .u64 t; cvta.to.shared.u64 t, %1; cvt.u32.u64 %0, t; }" : "=r"(a) : "l"(p));
    return a;
}
__device__ __forceinline__ void cp_async16(uint32_t saddr, const void* gaddr) {
    asm volatile("cp.async.cg.shared.global [%0], [%1], 16;" :: "r"(saddr), "l"(gaddr));
}
__device__ __forceinline__ void cp_commit() { asm volatile("cp.async.commit_group;"); }
__device__ __forceinline__ void cp_wait1()  { asm volatile("cp.async.wait_group 1;" ::: "memory"); }

__device__ __forceinline__ void ldsm_x4(uint32_t& r0, uint32_t& r1, uint32_t& r2, uint32_t& r3,
                                        uint32_t addr) {
    asm volatile("ldmatrix.sync.aligned.m8n8.x4.shared.b16 {%0,%1,%2,%3}, [%4];"
                 : "=r"(r0), "=r"(r1), "=r"(r2), "=r"(r3) : "r"(addr));
}
__device__ __forceinline__ void mma_bf16(float* c, const uint32_t* a, uint32_t b0, uint32_t b1) {
    asm volatile("mma.sync.aligned.m16n8k16.row.col.f32.bf16.bf16.f32 "
                 "{%0,%1,%2,%3}, {%4,%5,%6,%7}, {%8,%9}, {%0,%1,%2,%3};"
                 : "+f"(c[0]), "+f"(c[1]), "+f"(c[2]), "+f"(c[3])
                 : "r"(a[0]), "r"(a[1]), "r"(a[2]), "r"(a[3]), "r"(b0), "r"(b1));
}

// A-resident swizzle for 512-col bf16 rows (64 x 16B chunks per row)
#define SWA(r, c) ((r) * 1024 + ((((c) & 0x38) | (((c) & 7) ^ ((r) & 7))) << 4))

// ---------------------------------------------------------------------------
// c2 / zz
// ---------------------------------------------------------------------------
__global__ void c2_kernel(const float* __restrict__ cb) {
    int row  = blockIdx.x * 8 + (threadIdx.x >> 5);
    int lane = threadIdx.x & 31;
    const float* p = cb + (size_t)row * D_;
    float s = 0.f;
    #pragma unroll 4
    for (int i = lane; i < D_; i += 32) { float v = p[i]; s += v * v; }
    #pragma unroll
    for (int o = 16; o; o >>= 1) s += __shfl_xor_sync(0xffffffffu, s, o);
    if (lane == 0) g_c2[row] = s;
}

__global__ void zz_kernel() {
    int row  = blockIdx.x * 8 + (threadIdx.x >> 5);
    int lane = threadIdx.x & 31;
    const float* p = g_ze + (size_t)row * D_;
    double s = 0.0;
    #pragma unroll 4
    for (int i = lane; i < D_; i += 32) { double v = (double)p[i]; s += v * v; }
    #pragma unroll
    for (int o = 16; o; o >>= 1) s += __shfl_xor_sync(0xffffffffu, s, o);
    if (lane == 0) g_zz[row] = (float)s;
}

// ---------------------------------------------------------------------------
// Pack kernels
// ---------------------------------------------------------------------------
__global__ void pack_x_kernel(const float* __restrict__ x) {
    const int row = blockIdx.x, t = threadIdx.x;     // 256 thr, 4 cols each (DIN=1024)
    float4 v = *reinterpret_cast<const float4*>(x + (size_t)row * DIN + t * 4);
    __nv_bfloat162 h01, h23, l01, l23;
    h01.x = __float2bfloat16_rn(v.x); h01.y = __float2bfloat16_rn(v.y);
    h23.x = __float2bfloat16_rn(v.z); h23.y = __float2bfloat16_rn(v.w);
    l01.x = __float2bfloat16_rn(v.x - __bfloat162float(h01.x));
    l01.y = __float2bfloat16_rn(v.y - __bfloat162float(h01.y));
    l23.x = __float2bfloat16_rn(v.z - __bfloat162float(h23.x));
    l23.y = __float2bfloat16_rn(v.w - __bfloat162float(h23.y));
    __nv_bfloat162* d = reinterpret_cast<__nv_bfloat162*>(g_xs + (size_t)row * KP2 + t * 4);
    d[0] = h01; d[1] = h23;            // [0,1024): a0
    d += 512;  d[0] = h01; d[1] = h23; // [1024,2048): a0
    d += 512;  d[0] = l01; d[1] = l23; // [2048,3072): a1
}

__global__ void pack_w_kernel(const float* __restrict__ w) {
    const int row = blockIdx.x, t = threadIdx.x;
    float4 v = *reinterpret_cast<const float4*>(w + (size_t)row * DIN + t * 4);
    __nv_bfloat162 h01, h23, l01, l23;
    h01.x = __float2bfloat16_rn(v.x); h01.y = __float2bfloat16_rn(v.y);
    h23.x = __float2bfloat16_rn(v.z); h23.y = __float2bfloat16_rn(v.w);
    l01.x = __float2bfloat16_rn(v.x - __bfloat162float(h01.x));
    l01.y = __float2bfloat16_rn(v.y - __bfloat162float(h01.y));
    l23.x = __float2bfloat16_rn(v.z - __bfloat162float(h23.x));
    l23.y = __float2bfloat16_rn(v.w - __bfloat162float(h23.y));
    __nv_bfloat162* d = reinterpret_cast<__nv_bfloat162*>(g_ws + (size_t)row * KP2 + t * 4);
    d[0] = h01; d[1] = h23;            // [0,1024): b0
    d += 512;  d[0] = l01; d[1] = l23; // [1024,2048): b1
    d += 512;  d[0] = h01; d[1] = h23; // [2048,3072): b0
}

__global__ void pack_cb_kernel(const float* __restrict__ cb) {
    size_t i = ((size_t)blockIdx.x * 256 + threadIdx.x) * 2;
    float2 v = *reinterpret_cast<const float2*>(cb + i);
    __nv_bfloat162 h; h.x = __float2bfloat16_rn(v.x); h.y = __float2bfloat16_rn(v.y);
    *reinterpret_cast<__nv_bfloat162*>(g_cbb + i) = h;
}

__global__ void pack_zb_kernel() {
    size_t i = ((size_t)blockIdx.x * 256 + threadIdx.x) * 2;
    float2 v = *reinterpret_cast<const float2*>(g_ze + i);
    __nv_bfloat162 h; h.x = __float2bfloat16_rn(v.x); h.y = __float2bfloat16_rn(v.y);
    *reinterpret_cast<__nv_bfloat162*>(g_zb + i) = h;
}

// ---------------------------------------------------------------------------
// GEMM1 via mma.sync: z_e = x @ W^T with packed 3-split (K''=3072).
// Block 128x128, 8 warps, 3-stage cp.async pipeline. grid (4, 128).
// ---------------------------------------------------------------------------
#define NS1    3
#define BLKK   64
#define STAGEB 16384
#define SM1_B  (NS1 * STAGEB)
#define SM1TOT (2 * NS1 * STAGEB)   // 96KB

__global__ __launch_bounds__(256, 1) void gemm1_mma_kernel() {
    extern __shared__ char sm[];
    const uint32_t sbase = smem_u32(sm);
    const int tid  = threadIdx.x;
    const int lane = tid & 31;
    const int wid  = tid >> 5;
    const int warp_m = wid & 1;
    const int warp_n = wid >> 1;
    const int row0 = blockIdx.y * 128;
    const int col0 = blockIdx.x * 128;
    const int NKIT = KP2 / BLKK;      // 48

    const __nv_bfloat16* gA = g_xs + (size_t)row0 * KP2;
    const __nv_bfloat16* gB = g_ws + (size_t)col0 * KP2;

    float acc[4][4][4];
    #pragma unroll
    for (int mf = 0; mf < 4; mf++)
        #pragma unroll
        for (int nf = 0; nf < 4; nf++)
            #pragma unroll
            for (int q = 0; q < 4; q++) acc[mf][nf][q] = 0.f;

    #define G1_ISSUE(stg, kit) do {                                                \
        const uint32_t As_ = sbase + (stg) * STAGEB;                               \
        const uint32_t Bs_ = sbase + SM1_B + (stg) * STAGEB;                       \
        const int koff_ = (kit) * BLKK;                                            \
        _Pragma("unroll")                                                          \
        for (int i_ = 0; i_ < 4; i_++) {                                           \
            int id_ = tid + i_ * 256;                                              \
            int r_  = id_ >> 3;                                                    \
            int c_  = id_ & 7;                                                     \
            int cp_ = c_ ^ (r_ & 7);                                               \
            cp_async16(As_ + r_ * 128 + cp_ * 16, gA + (size_t)r_ * KP2 + koff_ + c_ * 8); \
            cp_async16(Bs_ + r_ * 128 + cp_ * 16, gB + (size_t)r_ * KP2 + koff_ + c_ * 8); \
        }                                                                          \
    } while (0)

    G1_ISSUE(0, 0); cp_commit();
    G1_ISSUE(1, 1); cp_commit();

    const int g = lane >> 3;
    const int r8 = lane & 7;

    for (int kit = 0; kit < NKIT; kit++) {
        cp_wait1();
        __syncthreads();
        if (kit + 2 < NKIT) G1_ISSUE((kit + 2) % NS1, kit + 2);
        cp_commit();

        const int stg = kit % NS1;
        const uint32_t Abase = sbase + stg * STAGEB;
        const uint32_t Bbase = sbase + SM1_B + stg * STAGEB;

        #pragma unroll
        for (int ks = 0; ks < 4; ks++) {
            uint32_t afr[4][4];
            #pragma unroll
            for (int mf = 0; mf < 4; mf++) {
                int rr = warp_m * 64 + mf * 16 + ((g & 1) << 3) + r8;
                int ch = 2 * ks + (g >> 1);
                ldsm_x4(afr[mf][0], afr[mf][1], afr[mf][2], afr[mf][3],
                        Abase + rr * 128 + ((ch ^ (rr & 7)) << 4));
            }
            uint32_t bfr[2][4];
            #pragma unroll
            for (int nf2 = 0; nf2 < 2; nf2++) {
                int rr = warp_n * 32 + nf2 * 16 + ((g >> 1) << 3) + r8;
                int ch = 2 * ks + (g & 1);
                ldsm_x4(bfr[nf2][0], bfr[nf2][1], bfr[nf2][2], bfr[nf2][3],
                        Bbase + rr * 128 + ((ch ^ (rr & 7)) << 4));
            }
            #pragma unroll
            for (int mf = 0; mf < 4; mf++)
                #pragma unroll
                for (int nf = 0; nf < 4; nf++)
                    mma_bf16(acc[mf][nf], afr[mf],
                             bfr[nf >> 1][(nf & 1) * 2], bfr[nf >> 1][(nf & 1) * 2 + 1]);
        }
    }
    #undef G1_ISSUE

    // store z_e
    #pragma unroll
    for (int mf = 0; mf < 4; mf++)
        #pragma unroll
        for (int h = 0; h < 2; h++) {
            const int row = row0 + warp_m * 64 + mf * 16 + h * 8 + (lane >> 2);
            #pragma unroll
            for (int nf = 0; nf < 4; nf++) {
                const int col = col0 + warp_n * 32 + nf * 8 + (lane & 3) * 2;
                float2 o; o.x = acc[mf][nf][h * 2]; o.y = acc[mf][nf][h * 2 + 1];
                *reinterpret_cast<float2*>(g_ze + (size_t)row * D_ + col) = o;
            }
        }
}

// ---------------------------------------------------------------------------
// Phase 1: single-pass bf16 approx GEMM, stores s = c2 - 2*dot to g_dist.
// A (128 rows x 512 bf16 = 128KB) resident in smem; B streamed, 3-stage ring.
// grid (8, 128): bx -> codes [bx*1024, +1024), by -> rows [by*128, +128).
// ---------------------------------------------------------------------------
#define P1_SM_A  0
#define P1_SM_B  131072
#define P1_SMTOT (131072 + 3 * STAGEB)   // 180224

__global__ __launch_bounds__(256, 1) void phase1_kernel() {
    extern __shared__ char sm[];
    const uint32_t sbase = smem_u32(sm);
    const int tid  = threadIdx.x;
    const int lane = tid & 31;
    const int wid  = tid >> 5;
    const int warp_m = wid & 1;
    const int warp_n = wid >> 1;
    const int row0 = blockIdx.y * 128;
    const int code_base = blockIdx.x * 1024;

    // resident A: 128 rows x 64 chunks(16B)
    {
        const __nv_bfloat16* gA = g_zb + (size_t)row0 * D_;
        #pragma unroll
        for (int i = 0; i < 32; i++) {
            int idx = tid + i * 256;
            int r   = idx >> 6;
            int c16 = idx & 63;
            cp_async16(sbase + P1_SM_A + SWA(r, c16), gA + (size_t)r * D_ + c16 * 8);
        }
    }
    cp_commit();   // group: A

    #define P1_ISSUE(stg, u) do {                                                  \
        const uint32_t Bs_ = sbase + P1_SM_B + (stg) * STAGEB;                     \
        const int nt_ = (u) >> 3, kit_ = (u) & 7;                                  \
        const __nv_bfloat16* gB_ = g_cbb + (size_t)(code_base + nt_ * 128) * D_;   \
        _Pragma("unroll")                                                          \
        for (int i_ = 0; i_ < 4; i_++) {                                           \
            int id_ = tid + i_ * 256;                                              \
            int r_  = id_ >> 3;                                                    \
            int c_  = id_ & 7;                                                     \
            cp_async16(Bs_ + r_ * 128 + ((c_ ^ (r_ & 7)) << 4),                    \
                       gB_ + (size_t)r_ * D_ + kit_ * BLKK + c_ * 8);              \
        }                                                                          \
    } while (0)

    P1_ISSUE(0, 0); cp_commit();
    P1_ISSUE(1, 1); cp_commit();

    const int g = lane >> 3;
    const int r8 = lane & 7;
    float acc[4][4][4];

    for (int u = 0; u < 64; u++) {
        const int nt = u >> 3, kit = u & 7;
        cp_wait1();
        __syncthreads();
        if (u + 2 < 64) P1_ISSUE((u + 2) % 3, u + 2);
        cp_commit();

        if (kit == 0) {
            #pragma unroll
            for (int mf = 0; mf < 4; mf++)
                #pragma unroll
                for (int nf = 0; nf < 4; nf++)
                    #pragma unroll
                    for (int q = 0; q < 4; q++) acc[mf][nf][q] = 0.f;
        }

        const uint32_t Bbase = sbase + P1_SM_B + (u % 3) * STAGEB;
        #pragma unroll
        for (int ks = 0; ks < 4; ks++) {
            uint32_t afr[4][4];
            #pragma unroll
            for (int mf = 0; mf < 4; mf++) {
                int rr  = warp_m * 64 + mf * 16 + ((g & 1) << 3) + r8;
                int c16 = kit * 8 + 2 * ks + (g >> 1);
                ldsm_x4(afr[mf][0], afr[mf][1], afr[mf][2], afr[mf][3],
                        sbase + P1_SM_A + SWA(rr, c16));
            }
            uint32_t bfr[2][4];
            #pragma unroll
            for (int nf2 = 0; nf2 < 2; nf2++) {
                int rr = warp_n * 32 + nf2 * 16 + ((g >> 1) << 3) + r8;
                int ch = 2 * ks + (g & 1);
                ldsm_x4(bfr[nf2][0], bfr[nf2][1], bfr[nf2][2], bfr[nf2][3],
                        Bbase + rr * 128 + ((ch ^ (rr & 7)) << 4));
            }
            #pragma unroll
            for (int mf = 0; mf < 4; mf++)
                #pragma unroll
                for (int nf = 0; nf < 4; nf++)
                    mma_bf16(acc[mf][nf], afr[mf],
                             bfr[nf >> 1][(nf & 1) * 2], bfr[nf >> 1][(nf & 1) * 2 + 1]);
        }

        if (kit == 7) {   // tile done: store approx scores
            #pragma unroll
            for (int nf = 0; nf < 4; nf++) {
                const int code0 = code_base + nt * 128 + warp_n * 32 + nf * 8 + (lane & 3) * 2;
                const float c2a = __ldg(&g_c2[code0]);
                const float c2b = __ldg(&g_c2[code0 + 1]);
                #pragma unroll
                for (int mf = 0; mf < 4; mf++)
                    #pragma unroll
                    for (int h = 0; h < 2; h++) {
                        const int row = row0 + warp_m * 64 + mf * 16 + h * 8 + (lane >> 2);
                        float2 o;
                        o.x = c2a - 2.0f * acc[mf][nf][h * 2 + 0];
                        o.y = c2b - 2.0f * acc[mf][nf][h * 2 + 1];
                        *reinterpret_cast<float2*>(g_dist + (size_t)row * K_ + code0) = o;
                    }
            }
        }
    }
    #undef P1_ISSUE
}

// ---------------------------------------------------------------------------
// Phase 2: per-row scan of approx scores -> candidates -> exact fp64 rescore
// with reference-grid fp32 rounding + index tie-break. 1 warp per row.
// ---------------------------------------------------------------------------
#define MARGIN 0.04f
#define CAP    32

__global__ __launch_bounds__(256) void phase2_kernel(const float* __restrict__ cb) {
    __shared__ int s_cnt[8];
    __shared__ int s_list[8][CAP];
    const int wid  = threadIdx.x >> 5;
    const int lane = threadIdx.x & 31;
    const int row  = blockIdx.x * 8 + wid;

    const float4* dp = reinterpret_cast<const float4*>(g_dist + (size_t)row * K_);

    // sweep 1: min
    float mn = 3.4e38f;
    #pragma unroll 8
    for (int i = 0; i < 64; i++) {
        float4 v = dp[lane + i * 32];
        mn = fminf(mn, fminf(fminf(v.x, v.y), fminf(v.z, v.w)));
    }
    #pragma unroll
    for (int o = 16; o; o >>= 1) mn = fminf(mn, __shfl_xor_sync(0xffffffffu, mn, o));

    if (lane == 0) s_cnt[wid] = 0;
    __syncwarp();
    const float thr = mn + MARGIN;

    // sweep 2: collect candidates (L2-hot)
    #pragma unroll 4
    for (int i = 0; i < 64; i++) {
        float4 v = dp[lane + i * 32];
        const int k0 = (lane + i * 32) * 4;
        if (v.x < thr) { int p = atomicAdd(&s_cnt[wid], 1); if (p < CAP) s_list[wid][p] = k0; }
        if (v.y < thr) { int p = atomicAdd(&s_cnt[wid], 1); if (p < CAP) s_list[wid][p] = k0 + 1; }
        if (v.z < thr) { int p = atomicAdd(&s_cnt[wid], 1); if (p < CAP) s_list[wid][p] = k0 + 2; }
        if (v.w < thr) { int p = atomicAdd(&s_cnt[wid], 1); if (p < CAP) s_list[wid][p] = k0 + 3; }
    }
    __syncwarp();
    int n = s_cnt[wid]; if (n > CAP) n = CAP;

    // exact rescore
    const float* ze = g_ze + (size_t)row * D_;
    const float  zz = g_zz[row];
    float bv = 3.4e38f;
    int   bi = 0x7fffffff;
    for (int c = 0; c < n; c++) {
        const int k = s_list[wid][c];
        const float* cr = cb + (size_t)k * D_;
        double d = 0.0;
        #pragma unroll
        for (int j = 0; j < 16; j++) {
            int dd = lane + j * 32;
            d = fma((double)ze[dd], (double)cr[dd], d);
        }
        #pragma unroll
        for (int o = 16; o; o >>= 1) d += __shfl_xor_sync(0xffffffffu, d, o);
        float t = __fadd_rn(zz, -2.0f * (float)d);   // fl32(zz - 2*dot)
        float v = __fadd_rn(t, g_c2[k]);             // fl32(... + |c|^2)
        if (v < bv || (v == bv && k < bi)) { bv = v; bi = k; }
    }
    if (lane == 0) g_idx[row] = bi;
}

// ---------------------------------------------------------------------------
// Output assembly
// ---------------------------------------------------------------------------
__global__ void output_kernel(const float* __restrict__ cb, float* __restrict__ out) {
    const int b   = blockIdx.x;
    const int tid = threadIdx.x;
    const int idx = g_idx[b];

    const float* ze = g_ze + (size_t)b * D_;
    const float* zq = cb   + (size_t)idx * D_;
    float*       o  = out  + (size_t)b * D_;

    float s = 0.f;
    #pragma unroll
    for (int d = tid; d < D_; d += 128) {
        float e    = ze[d];
        float q    = zq[d];
        float diff = q - e;
        o[d] = e + diff;
        s += diff * diff;
    }
    __shared__ float red[128];
    red[tid] = s;
    __syncthreads();
    #pragma unroll
    for (int o2 = 64; o2; o2 >>= 1) {
        if (tid < o2) red[tid] += red[tid + o2];
        __syncthreads();
    }
    if (tid == 0) {
        out[(size_t)B_ * D_ + b]      = (float)idx;
        out[(size_t)B_ * D_ + B_ + b] = red[0] / (float)D_;
    }
}

// ---------------------------------------------------------------------------
extern "C" void kernel_launch(void* const* d_in, const int* in_sizes, int n_in,
                              void* d_out, int out_size) {
    const float* x  = (const float*)d_in[0];
    const float* W  = (const float*)d_in[1];
    const float* cb = (const float*)d_in[2];
    float* out = (float*)d_out;
    (void)in_sizes; (void)n_in; (void)out_size;

    cudaFuncSetAttribute(gemm1_mma_kernel, cudaFuncAttributeMaxDynamicSharedMemorySize, SM1TOT);
    cudaFuncSetAttribute(phase1_kernel,    cudaFuncAttributeMaxDynamicSharedMemorySize, P1_SMTOT);

    pack_x_kernel<<<B_, 256>>>(x);
    pack_w_kernel<<<D_, 256>>>(W);
    c2_kernel<<<K_ / 8, 256>>>(cb);
    pack_cb_kernel<<<(int)(((size_t)K_ * D_) / 512), 256>>>(cb);
    gemm1_mma_kernel<<<dim3(4, 128), 256, SM1TOT>>>();
    zz_kernel<<<B_ / 8, 256>>>();
    pack_zb_kernel<<<(int)(((size_t)B_ * D_) / 512), 256>>>();
    phase1_kernel<<<dim3(8, 128), 256, P1_SMTOT>>>();
    phase2_kernel<<<B_ / 8, 256>>>(cb);
    output_kernel<<<B_, 128>>>(cb, out);
}